// round 1
// baseline (speedup 1.0000x reference)
#include <cuda_runtime.h>
#include <cuda_bf16.h>
#include <math.h>

// ---------------- problem constants ----------------
constexpr int cT   = 2048;
constexpr int cD   = 1024;
constexpr int cV   = 32000;
constexpr int cE   = 16;
constexpr int cK   = 2;       // topk
constexpr int cCAP = 512;
constexpr int cH   = 16;
constexpr int cDH  = 64;
constexpr int cDFF = 4096;
constexpr int cHOPS= 2;

// ---------------- device scratch (no cudaMalloc allowed) ----------------
__device__ float g_h   [cT * cD];                 // hidden state [T,D]
__device__ float g_hn  [cT * cD];                 // normalized hidden
__device__ float g_cos [cT * cDH];
__device__ float g_sin [cT * cDH];
__device__ float g_logits[cT * cE];
__device__ float g_probs [cT * cE];
__device__ unsigned char g_mask[cT * cE];
__device__ int   g_kept_slot[cT * cE];            // slot index or -1
__device__ int   g_counts[cE];
__device__ int   g_etok[cE * cCAP];               // token id per slot
__device__ float g_xin [(long)cE * cCAP * cD];    // 32 MB
__device__ float g_mid [(long)cE * cCAP * cDFF];  // 128 MB
__device__ float g_eout[(long)cE * cCAP * cD];    // 32 MB

// ---------------- small kernels ----------------
__global__ void rope_init_kernel() {
    int t = blockIdx.x;
    int i = threadIdx.x;               // 0..63
    int j = 2 * (i & 31);              // 0,2,...,62
    float inv = powf(10000.0f, -(float)j / (float)cDH);
    float fr  = (float)t * inv;
    g_cos[t * cDH + i] = cosf(fr);
    g_sin[t * cDH + i] = sinf(fr);
}

__global__ void embed_gather_kernel(const int* __restrict__ ids,
                                    const float* __restrict__ ew) {
    long idx = (long)blockIdx.x * blockDim.x + threadIdx.x;
    if (idx >= (long)cT * cD) return;
    int t = (int)(idx >> 10);
    int d = (int)(idx & (cD - 1));
    g_h[idx] = ew[(long)ids[t] * cD + d];
}

// logits[t,e] = h[t,:] @ wr[:,e] ; one block per token, 16 warps (one per expert)
__global__ void router_logits_kernel(const float* __restrict__ wr) {
    int t    = blockIdx.x;
    int e    = threadIdx.x >> 5;
    int lane = threadIdx.x & 31;
    float s = 0.f;
    const float* hp = &g_h[(long)t * cD];
    for (int d = lane; d < cD; d += 32)
        s += hp[d] * wr[(long)d * cE + e];
    #pragma unroll
    for (int o = 16; o; o >>= 1) s += __shfl_down_sync(0xffffffffu, s, o);
    if (lane == 0) g_logits[t * cE + e] = s;
}

// per-token: softmax, top-2 mask, reset kept slots; also reset expert counts
__global__ void token_route_kernel() {
    int t = blockIdx.x * blockDim.x + threadIdx.x;
    if (t >= cT) return;
    float l[cE];
    #pragma unroll
    for (int e = 0; e < cE; e++) l[e] = g_logits[t * cE + e];
    // top-1 (ties -> lower index, matching jax.lax.top_k)
    int i1 = 0; float v1 = l[0];
    #pragma unroll
    for (int e = 1; e < cE; e++) if (l[e] > v1) { v1 = l[e]; i1 = e; }
    // top-2
    int i2 = -1; float v2 = -INFINITY;
    #pragma unroll
    for (int e = 0; e < cE; e++) if (e != i1 && l[e] > v2) { v2 = l[e]; i2 = e; }
    // softmax
    float sum = 0.f; float p[cE];
    #pragma unroll
    for (int e = 0; e < cE; e++) { p[e] = expf(l[e] - v1); sum += p[e]; }
    float invs = 1.0f / sum;
    #pragma unroll
    for (int e = 0; e < cE; e++) {
        g_probs[t * cE + e] = p[e] * invs;
        g_mask [t * cE + e] = (e == i1 || e == i2) ? 1 : 0;
        g_kept_slot[t * cE + e] = -1;
    }
    if (t < cE) g_counts[t] = 0;
}

// per-expert capacity-512 selection by exact rank (value desc, index asc)
__global__ void capacity_kernel() {
    int e = blockIdx.x;
    __shared__ float sg[cT];
    __shared__ unsigned char sm[cT];
    for (int t = threadIdx.x; t < cT; t += blockDim.x) {
        sg[t] = g_logits[t * cE + e];
        sm[t] = g_mask  [t * cE + e];
    }
    __syncthreads();
    for (int t = threadIdx.x; t < cT; t += blockDim.x) {
        if (!sm[t]) continue;
        float v = sg[t];
        int rank = 0;
        for (int u = 0; u < cT; u++) {
            if (sm[u] && (sg[u] > v || (sg[u] == v && u < t))) rank++;
        }
        if (rank < cCAP) {
            int s = atomicAdd(&g_counts[e], 1);
            g_etok[e * cCAP + s] = t;
            g_kept_slot[t * cE + e] = s;
        }
    }
}

// gather token hidden into expert slot buffer + apply RoPE
__global__ void gather_rope_kernel() {
    int c = blockIdx.x;
    int e = blockIdx.y;
    if (c >= g_counts[e]) return;
    int t = g_etok[e * cCAP + c];
    __shared__ float x[cD];
    for (int d = threadIdx.x; d < cD; d += blockDim.x) x[d] = g_h[(long)t * cD + d];
    __syncthreads();
    const float* cs = &g_cos[t * cDH];
    const float* sn = &g_sin[t * cDH];
    float* out = &g_xin[((long)(e * cCAP + c)) * cD];
    for (int d = threadIdx.x; d < cD; d += blockDim.x) {
        int i = d & (cDH - 1);
        float r = (i < 32) ? -x[d + 32] : x[d - 32];
        out[d] = x[d] * cs[i] + r * sn[i];
    }
}

// combine expert outputs back to tokens: h = h + sum(p*out) - rho*h
__global__ void combine_kernel() {
    int t = blockIdx.x;
    int ne = 0;
    int  ks[cK]; float kp[cK]; int ke[cK];
    float rho = 0.f;
    #pragma unroll
    for (int e = 0; e < cE; e++) {
        int s = g_kept_slot[t * cE + e];
        if (s >= 0) {
            float p = g_probs[t * cE + e];
            rho += p;
            if (ne < cK) { ke[ne] = e; ks[ne] = s; kp[ne] = p; ne++; }
        }
    }
    for (int d = threadIdx.x; d < cD; d += blockDim.x) {
        float hv = g_h[(long)t * cD + d];
        float comb = 0.f;
        for (int q = 0; q < ne; q++)
            comb += kp[q] * g_eout[((long)(ke[q] * cCAP + ks[q])) * cD + d];
        g_h[(long)t * cD + d] = hv + comb - rho * hv;
    }
}

__global__ void rmsnorm_kernel(const float* __restrict__ lns) {
    int t = blockIdx.x;
    __shared__ float red[256];
    float s = 0.f;
    for (int d = threadIdx.x; d < cD; d += 256) {
        float v = g_h[(long)t * cD + d];
        s += v * v;
    }
    red[threadIdx.x] = s;
    __syncthreads();
    #pragma unroll
    for (int o = 128; o; o >>= 1) {
        if (threadIdx.x < o) red[threadIdx.x] += red[threadIdx.x + o];
        __syncthreads();
    }
    float inv = rsqrtf(red[0] / (float)cD + 1e-6f);
    for (int d = threadIdx.x; d < cD; d += 256)
        g_hn[(long)t * cD + d] = g_h[(long)t * cD + d] * lns[d] * inv;
}

// ---------------- SGEMM 128x128x8, 256 threads, 8x8 per thread ----------------
// C[M,N] = act( A[M,K] @ B )   A row-major (lda)
// TRANSB=0: B[k*ldb + n] ; TRANSB=1: B[n*ldb + k]
// batched over blockIdx.z with strides sA/sB/sC; per-batch M from Mvec if non-null
template<int TRANSB, int ACT>
__global__ void __launch_bounds__(256, 2)
sgemm_kernel(const float* __restrict__ A, const float* __restrict__ B,
             float* __restrict__ C,
             int M, int N, int Kd, int lda, int ldb, int ldc,
             long sA, long sB, long sC, const int* __restrict__ Mvec)
{
    constexpr int BM = 128, BN = 128, BK = 8;
    int e = blockIdx.z;
    if (Mvec) M = Mvec[e];
    int bm = blockIdx.y * BM;
    if (bm >= M) return;
    int bn = blockIdx.x * BN;
    A += (long)e * sA; B += (long)e * sB; C += (long)e * sC;

    __shared__ float As[BK][BM];
    __shared__ float Bs[BK][BN];

    int tid = threadIdx.x;
    int tx = tid & 15, ty = tid >> 4;

    float acc[8][8];
    #pragma unroll
    for (int i = 0; i < 8; i++)
        #pragma unroll
        for (int j = 0; j < 8; j++) acc[i][j] = 0.f;

    int arow = tid >> 1;
    int acol = (tid & 1) * 4;
    int brow = tid >> 5;
    int bcol = (tid & 31) * 4;
    int tkk  = tid & 7;
    int tn0  = tid >> 3;

    for (int k0 = 0; k0 < Kd; k0 += BK) {
        float4 av = make_float4(0.f, 0.f, 0.f, 0.f);
        if (bm + arow < M)
            av = *(const float4*)&A[(long)(bm + arow) * lda + k0 + acol];
        As[acol + 0][arow] = av.x;
        As[acol + 1][arow] = av.y;
        As[acol + 2][arow] = av.z;
        As[acol + 3][arow] = av.w;
        if (TRANSB) {
            #pragma unroll
            for (int j = 0; j < 4; j++) {
                int n = tn0 + 32 * j;
                Bs[tkk][n] = B[(long)(bn + n) * ldb + k0 + tkk];
            }
        } else {
            float4 bv = *(const float4*)&B[(long)(k0 + brow) * ldb + bn + bcol];
            *(float4*)&Bs[brow][bcol] = bv;
        }
        __syncthreads();
        #pragma unroll
        for (int kk = 0; kk < BK; kk++) {
            float4 a0 = *(const float4*)&As[kk][ty * 4];
            float4 a1 = *(const float4*)&As[kk][ty * 4 + 64];
            float4 b0 = *(const float4*)&Bs[kk][tx * 4];
            float4 b1 = *(const float4*)&Bs[kk][tx * 4 + 64];
            float ar[8] = {a0.x, a0.y, a0.z, a0.w, a1.x, a1.y, a1.z, a1.w};
            float br[8] = {b0.x, b0.y, b0.z, b0.w, b1.x, b1.y, b1.z, b1.w};
            #pragma unroll
            for (int i = 0; i < 8; i++)
                #pragma unroll
                for (int j = 0; j < 8; j++)
                    acc[i][j] = fmaf(ar[i], br[j], acc[i][j]);
        }
        __syncthreads();
    }

    #pragma unroll
    for (int i = 0; i < 8; i++) {
        int m = bm + ty * 4 + (i & 3) + (i >> 2) * 64;
        if (m >= M) continue;
        #pragma unroll
        for (int j = 0; j < 8; j++) {
            int n = bn + tx * 4 + (j & 3) + (j >> 2) * 64;
            if (n >= N) continue;
            float v = acc[i][j];
            if (ACT) {
                float xx = v;
                v = 0.5f * xx * (1.0f + tanhf(0.7978845608028654f *
                        (xx + 0.044715f * xx * xx * xx)));
            }
            C[(long)m * ldc + n] = v;
        }
    }
}

// ---------------- launch ----------------
extern "C" void kernel_launch(void* const* d_in, const int* in_sizes, int n_in,
                              void* d_out, int out_size) {
    const int*   ids      = (const int*)  d_in[0];
    const float* embed_w  = (const float*)d_in[1];
    const float* router_w = (const float*)d_in[2];
    const float* w1       = (const float*)d_in[3];
    const float* w2       = (const float*)d_in[4];
    const float* lns      = (const float*)d_in[5];
    float* out = (float*)d_out;

    float *p_xin, *p_mid, *p_eout, *p_hn;
    int   *p_counts;
    cudaGetSymbolAddress((void**)&p_xin,    g_xin);
    cudaGetSymbolAddress((void**)&p_mid,    g_mid);
    cudaGetSymbolAddress((void**)&p_eout,   g_eout);
    cudaGetSymbolAddress((void**)&p_hn,     g_hn);
    cudaGetSymbolAddress((void**)&p_counts, g_counts);

    rope_init_kernel<<<cT, 64>>>();
    embed_gather_kernel<<<(int)(((long)cT * cD + 255) / 256), 256>>>(ids, embed_w);

    for (int hop = 0; hop < cHOPS; hop++) {
        router_logits_kernel<<<cT, 512>>>(router_w + (long)hop * cD * cE);
        token_route_kernel<<<(cT + 255) / 256, 256>>>();
        capacity_kernel<<<cE, 256>>>();
        gather_rope_kernel<<<dim3(cCAP, cE), 256>>>();
        // mid = gelu(xin @ w1[e])   [cnt_e,1024] x [1024,4096]
        sgemm_kernel<0, 1><<<dim3(cDFF / 128, cCAP / 128, cE), 256>>>(
            p_xin, w1, p_mid,
            cCAP, cDFF, cD, cD, cDFF, cDFF,
            (long)cCAP * cD, (long)cD * cDFF, (long)cCAP * cDFF, p_counts);
        // eout = mid @ w2[e]        [cnt_e,4096] x [4096,1024]
        sgemm_kernel<0, 0><<<dim3(cD / 128, cCAP / 128, cE), 256>>>(
            p_mid, w2, p_eout,
            cCAP, cD, cDFF, cDFF, cD, cD,
            (long)cCAP * cDFF, (long)cDFF * cD, (long)cCAP * cD, p_counts);
        combine_kernel<<<cT, 256>>>();
    }

    rmsnorm_kernel<<<cT, 256>>>(lns);
    // logits = hn @ embed_w^T   [2048,1024] x [1024,32000] (B transposed)
    sgemm_kernel<1, 0><<<dim3(cV / 128, cT / 128, 1), 256>>>(
        p_hn, embed_w, out,
        cT, cV, cD, cD, cD, cV,
        0, 0, 0, nullptr);
}